// round 1
// baseline (speedup 1.0000x reference)
#include <cuda_runtime.h>
#include <math.h>

#define NXY 256
#define NT  24
#define NC  16

// ---------------- scratch (__device__ globals: the sanctioned scratch path) ----
__device__ float2 g_warped[NT][NXY][NXY];      // (-1)^(x+y) * warp_t(img)      12.6 MB
__device__ float2 g_smapsT[NC][NXY][NXY];      // smaps transposed to [c][x][y]  8.4 MB
__device__ float2 g_G[NC][NT][NXY][NXY];       // row-FFT intermediate [c][t][ky][x] 201 MB
__device__ float2 g_outT[NC][NXY][NXY];        // result [c][ky][kx]             8.4 MB

// ---------------- complex helpers ---------------------------------------------
__device__ __forceinline__ float2 cmul(float2 a, float2 b){
    return make_float2(fmaf(a.x, b.x, -a.y*b.y), fmaf(a.x, b.y, a.y*b.x));
}
__device__ __forceinline__ float2 cadd(float2 a, float2 b){ return make_float2(a.x+b.x, a.y+b.y); }
__device__ __forceinline__ float2 csub(float2 a, float2 b){ return make_float2(a.x-b.x, a.y-b.y); }

// swizzle within blocks of 8 to break smem bank conflicts on bit-reversed scatter
__device__ __forceinline__ int swz(int k){ return (k & ~7) | ((k + (k >> 3)) & 7); }

// ---------------- 256-point complex FFT: one warp, 8 points/thread ------------
// Input : v[j] = x[32*j + L]   (L = lane)
// Output: v[j] = X[8*rev5(L) + RJ[j]],  RJ = {0,4,2,6,1,5,3,7}
// tw[m] = exp(-2*pi*i*m/256) in shared memory
__device__ __forceinline__ void fft256(float2 v[8], int L, const float2* __restrict__ tw)
{
    const float S2 = 0.70710678118654752f;
    // intra-thread radix-8 (DIF), output bit-reversed in register index
    float2 s0=cadd(v[0],v[4]), d0=csub(v[0],v[4]);
    float2 s1=cadd(v[1],v[5]), d1=csub(v[1],v[5]);
    float2 s2=cadd(v[2],v[6]), d2=csub(v[2],v[6]);
    float2 s3=cadd(v[3],v[7]), d3=csub(v[3],v[7]);
    d1 = cmul(d1, make_float2( S2,-S2));
    d2 = make_float2(d2.y, -d2.x);                 // * -i
    d3 = cmul(d3, make_float2(-S2,-S2));
    float2 e0=cadd(s0,s2), f0=csub(s0,s2);
    float2 e1=cadd(s1,s3), f1=csub(s1,s3);
    f1 = make_float2(f1.y, -f1.x);
    float2 e2=cadd(d0,d2), f2=csub(d0,d2);
    float2 e3=cadd(d1,d3), f3=csub(d1,d3);
    f3 = make_float2(f3.y, -f3.x);
    v[0]=cadd(e0,e1); v[1]=csub(e0,e1);
    v[2]=cadd(f0,f1); v[3]=csub(f0,f1);
    v[4]=cadd(e2,e3); v[5]=csub(e2,e3);
    v[6]=cadd(f2,f3); v[7]=csub(f2,f3);

    // twiddle by w256^{L * r_j}
    const int RJ[8] = {0,4,2,6,1,5,3,7};
    #pragma unroll
    for (int j = 1; j < 8; ++j)
        v[j] = cmul(v[j], tw[(L * RJ[j]) & 255]);

    // cross-lane radix-2 DIF FFT-32 via shfl_xor (output lane-bit-reversed)
    #pragma unroll
    for (int hs = 0; hs < 5; ++hs) {
        const int h = 16 >> hs;
        const int i = L & (h - 1);
        float2 W = tw[(i * (128 / h)) & 255];      // w_{2h}^i
        const bool up = (L & h) != 0;
        #pragma unroll
        for (int j = 0; j < 8; ++j) {
            float2 o;
            o.x = __shfl_xor_sync(0xffffffffu, v[j].x, h);
            o.y = __shfl_xor_sync(0xffffffffu, v[j].y, h);
            float2 su = make_float2(v[j].x + o.x, v[j].y + o.y);
            float2 df = cmul(make_float2(o.x - v[j].x, o.y - v[j].y), W);
            v[j] = up ? df : su;
        }
    }
}

// ---------------- kernel 1: bilinear warp, fold (-1)^(x+y) ---------------------
__global__ void __launch_bounds__(256) warp_kernel(const float* __restrict__ ir,
                                                   const float* __restrict__ ii,
                                                   const float* __restrict__ flow)
{
    const int x = blockIdx.x;
    const int y = threadIdx.x;
    const float sgn = ((x + y) & 1) ? -1.f : 1.f;
    const float4* p = (const float4*)(flow + ((size_t)x * NXY + y) * 48);

    #pragma unroll
    for (int q = 0; q < 6; ++q) {
        float4 fx4 = p[q];        // flow[..,0, t=4q..4q+3]
        float4 fy4 = p[q + 6];    // flow[..,1, t=4q..4q+3]
        float fxs[4] = {fx4.x, fx4.y, fx4.z, fx4.w};
        float fys[4] = {fy4.x, fy4.y, fy4.z, fy4.w};
        #pragma unroll
        for (int u = 0; u < 4; ++u) {
            int t = 4*q + u;
            float px = fminf(fmaxf((float)x + fxs[u], 0.f), 255.f);
            float py = fminf(fmaxf((float)y + fys[u], 0.f), 255.f);
            int x0 = (int)floorf(px); if (x0 > 254) x0 = 254;
            int y0 = (int)floorf(py); if (y0 > 254) y0 = 254;
            float wx = px - (float)x0, wy = py - (float)y0;
            int b = x0 * NXY + y0;
            float a0 = (1.f - wx) * (1.f - wy);
            float a1 = (1.f - wx) * wy;
            float a2 = wx * (1.f - wy);
            float a3 = wx * wy;
            float re = a0*ir[b] + a1*ir[b+1] + a2*ir[b+NXY] + a3*ir[b+NXY+1];
            float im = a0*ii[b] + a1*ii[b+1] + a2*ii[b+NXY] + a3*ii[b+NXY+1];
            g_warped[t][x][y] = make_float2(sgn * re, sgn * im);
        }
    }
}

// ---------------- kernel 2: smaps -> [c][x][y] float2 --------------------------
__global__ void __launch_bounds__(256) smaps_kernel(const float* __restrict__ sr,
                                                    const float* __restrict__ si)
{
    const int x = blockIdx.x;
    const int y = threadIdx.x;
    const float4* pr = (const float4*)(sr + ((size_t)x * NXY + y) * NC);
    const float4* pi = (const float4*)(si + ((size_t)x * NXY + y) * NC);
    float r[16], m[16];
    #pragma unroll
    for (int q = 0; q < 4; ++q) {
        float4 a = pr[q]; r[4*q]=a.x; r[4*q+1]=a.y; r[4*q+2]=a.z; r[4*q+3]=a.w;
        float4 b = pi[q]; m[4*q]=b.x; m[4*q+1]=b.y; m[4*q+2]=b.z; m[4*q+3]=b.w;
    }
    #pragma unroll
    for (int c = 0; c < 16; ++c)
        g_smapsT[c][x][y] = make_float2(r[c], m[c]);
}

// ---------------- kernel 3: row FFT along y, write transposed G ----------------
__global__ void __launch_bounds__(256) stage2_kernel()
{
    __shared__ float2 tile[8][256];
    __shared__ float2 tw[256];
    const int tid = threadIdx.x;
    {
        float s, c;
        sincosf(-6.283185307179586f * (float)tid / 256.f, &s, &c);
        tw[tid] = make_float2(c, s);
    }
    __syncthreads();

    const int warp = tid >> 5, L = tid & 31;
    const int xb = blockIdx.x, t = blockIdx.y, c = blockIdx.z;
    const int x = xb * 8 + warp;

    const float2* wr = &g_warped[t][x][0];
    const float2* sm = &g_smapsT[c][x][0];
    float2 v[8];
    #pragma unroll
    for (int j = 0; j < 8; ++j) v[j] = cmul(wr[32*j + L], sm[32*j + L]);

    fft256(v, L, tw);

    const int R = __brev((unsigned)L) >> 27;
    const int RJ[8] = {0,4,2,6,1,5,3,7};
    #pragma unroll
    for (int j = 0; j < 8; ++j)
        tile[warp][swz(8*R + RJ[j])] = v[j];
    __syncthreads();

    float2* dst = &g_G[c][t][0][xb * 8];
    #pragma unroll
    for (int i = 0; i < 8; ++i) {
        int idx = tid + i * 256;
        int ky = idx >> 3, xl = idx & 7;
        dst[(size_t)ky * NXY + xl] = tile[xl][swz(ky)];
    }
}

// ---------------- kernel 4: column FFT along x + masked t-sum ------------------
extern __shared__ float2 s3mem[];   // K[24][256] then tw[256]
__global__ void __launch_bounds__(256) stage3_kernel(const float* __restrict__ mask)
{
    float2* K  = s3mem;
    float2* tw = s3mem + NT * 256;
    const int tid = threadIdx.x;
    {
        float s, c;
        sincosf(-6.283185307179586f * (float)tid / 256.f, &s, &c);
        tw[tid] = make_float2(c, s);
    }
    __syncthreads();

    const int ky = blockIdx.x, c = blockIdx.y;
    const int warp = tid >> 5, L = tid & 31;
    const int RJ[8] = {0,4,2,6,1,5,3,7};

    for (int t = warp; t < NT; t += 8) {
        const float2* src = &g_G[c][t][ky][0];
        float2 v[8];
        #pragma unroll
        for (int j = 0; j < 8; ++j) v[j] = src[32*j + L];
        fft256(v, L, tw);
        const int R = __brev((unsigned)L) >> 27;
        #pragma unroll
        for (int j = 0; j < 8; ++j)
            K[t * 256 + swz(8*R + RJ[j])] = v[j];
    }
    __syncthreads();

    const int kx = tid;
    const float4* m4 = (const float4*)(mask + ((((size_t)kx * NXY + ky) * NC + c) * NT));
    float mm[24];
    #pragma unroll
    for (int q = 0; q < 6; ++q) {
        float4 f = __ldcs(m4 + q);
        mm[4*q] = f.x; mm[4*q+1] = f.y; mm[4*q+2] = f.z; mm[4*q+3] = f.w;
    }
    float ax = 0.f, ay = 0.f;
    const int sx = swz(kx);
    #pragma unroll
    for (int t = 0; t < NT; ++t) {
        float2 kv = K[t * 256 + sx];
        ax = fmaf(kv.x, mm[t], ax);
        ay = fmaf(kv.y, mm[t], ay);
    }
    const float s = ((kx + ky) & 1) ? -0.00390625f : 0.00390625f;  // (-1)^(kx+ky)/256
    g_outT[c][ky][kx] = make_float2(ax * s, ay * s);
}

// ---------------- kernel 5: repack to [2][Nx][Ny][Nc] --------------------------
__global__ void __launch_bounds__(256) final_kernel(float* __restrict__ out)
{
    const int x = blockIdx.x;
    const int y = threadIdx.x;
    float re[16], im[16];
    #pragma unroll
    for (int c = 0; c < 16; ++c) {
        float2 v = g_outT[c][y][x];
        re[c] = v.x; im[c] = v.y;
    }
    float* pr = out + ((size_t)x * NXY + y) * NC;
    float* pi = pr + (size_t)NXY * NXY * NC;
    #pragma unroll
    for (int q = 0; q < 4; ++q) {
        ((float4*)pr)[q] = make_float4(re[4*q], re[4*q+1], re[4*q+2], re[4*q+3]);
        ((float4*)pi)[q] = make_float4(im[4*q], im[4*q+1], im[4*q+2], im[4*q+3]);
    }
}

// ---------------- launch -------------------------------------------------------
extern "C" void kernel_launch(void* const* d_in, const int* in_sizes, int n_in,
                              void* d_out, int out_size)
{
    (void)in_sizes; (void)n_in; (void)out_size;
    const float* image_real = (const float*)d_in[0];
    const float* image_imag = (const float*)d_in[1];
    const float* mask       = (const float*)d_in[2];
    const float* smaps_real = (const float*)d_in[3];
    const float* smaps_imag = (const float*)d_in[4];
    const float* flow       = (const float*)d_in[5];

    const int s3_smem = (NT * 256 + 256) * (int)sizeof(float2);   // 51200 B
    cudaFuncSetAttribute(stage3_kernel, cudaFuncAttributeMaxDynamicSharedMemorySize, s3_smem);

    warp_kernel <<<256, 256>>>(image_real, image_imag, flow);
    smaps_kernel<<<256, 256>>>(smaps_real, smaps_imag);
    stage2_kernel<<<dim3(32, NT, NC), 256>>>();
    stage3_kernel<<<dim3(256, NC), 256, s3_smem>>>(mask);
    final_kernel<<<256, 256>>>((float*)d_out);
}

// round 2
// speedup vs baseline: 1.3230x; 1.3230x over previous
#include <cuda_runtime.h>
#include <math.h>

#define NXY 256
#define NT  24
#define NC  16
#define GRP 4      // coils per group (G slice stays L2-resident)

// ---------------- scratch ------------------------------------------------------
__device__ float2 g_warped[NT][NXY][NXY];      // (-1)^(x+y) * warp_t(img)   12.6 MB
__device__ float2 g_smapsT[NC][NXY][NXY];      // smaps [c][x][y]             8.4 MB
__device__ float2 g_G[GRP][NT][NXY][NXY];      // row-FFT interm, reused     50.3 MB
__device__ float2 g_outT[NC][NXY][NXY];        // result [c][ky][kx]          8.4 MB

// ---------------- complex helpers ---------------------------------------------
__device__ __forceinline__ float2 cmul(float2 a, float2 b){
    return make_float2(fmaf(a.x, b.x, -a.y*b.y), fmaf(a.x, b.y, a.y*b.x));
}
__device__ __forceinline__ float2 cadd(float2 a, float2 b){ return make_float2(a.x+b.x, a.y+b.y); }
__device__ __forceinline__ float2 csub(float2 a, float2 b){ return make_float2(a.x-b.x, a.y-b.y); }

// bank-decorrelating swizzle: low-3 bits mixed with bits [3:8) of the index
__device__ __forceinline__ int swz2(int k){ return (k & ~7) | ((k + (k >> 3) + (k >> 6)) & 7); }

// ---------------- 256-point complex FFT: one warp, 8 points/thread ------------
// Input : v[j] = x[32*j + L]   (L = lane)
// Output: v[j] = X[8*rev5(L) + RJ[j]],  RJ = {0,4,2,6,1,5,3,7}
__device__ __forceinline__ void fft256(float2 v[8], int L, const float2* __restrict__ tw)
{
    const float S2 = 0.70710678118654752f;
    float2 s0=cadd(v[0],v[4]), d0=csub(v[0],v[4]);
    float2 s1=cadd(v[1],v[5]), d1=csub(v[1],v[5]);
    float2 s2=cadd(v[2],v[6]), d2=csub(v[2],v[6]);
    float2 s3=cadd(v[3],v[7]), d3=csub(v[3],v[7]);
    d1 = cmul(d1, make_float2( S2,-S2));
    d2 = make_float2(d2.y, -d2.x);
    d3 = cmul(d3, make_float2(-S2,-S2));
    float2 e0=cadd(s0,s2), f0=csub(s0,s2);
    float2 e1=cadd(s1,s3), f1=csub(s1,s3);
    f1 = make_float2(f1.y, -f1.x);
    float2 e2=cadd(d0,d2), f2=csub(d0,d2);
    float2 e3=cadd(d1,d3), f3=csub(d1,d3);
    f3 = make_float2(f3.y, -f3.x);
    v[0]=cadd(e0,e1); v[1]=csub(e0,e1);
    v[2]=cadd(f0,f1); v[3]=csub(f0,f1);
    v[4]=cadd(e2,e3); v[5]=csub(e2,e3);
    v[6]=cadd(f2,f3); v[7]=csub(f2,f3);

    const int RJ[8] = {0,4,2,6,1,5,3,7};
    #pragma unroll
    for (int j = 1; j < 8; ++j)
        v[j] = cmul(v[j], tw[(L * RJ[j]) & 255]);

    #pragma unroll
    for (int hs = 0; hs < 5; ++hs) {
        const int h = 16 >> hs;
        const int i = L & (h - 1);
        float2 W = tw[(i * (128 / h)) & 255];
        const bool up = (L & h) != 0;
        #pragma unroll
        for (int j = 0; j < 8; ++j) {
            float2 o;
            o.x = __shfl_xor_sync(0xffffffffu, v[j].x, h);
            o.y = __shfl_xor_sync(0xffffffffu, v[j].y, h);
            float2 su = make_float2(v[j].x + o.x, v[j].y + o.y);
            float2 df = cmul(make_float2(o.x - v[j].x, o.y - v[j].y), W);
            v[j] = up ? df : su;
        }
    }
}

// ---------------- kernel 1: bilinear warp, fold (-1)^(x+y) ---------------------
__global__ void __launch_bounds__(256) warp_kernel(const float* __restrict__ ir,
                                                   const float* __restrict__ ii,
                                                   const float* __restrict__ flow)
{
    const int x = blockIdx.x;
    const int y = threadIdx.x;
    const int q = blockIdx.y;                 // t-quad: t = 4q..4q+3
    const float sgn = ((x + y) & 1) ? -1.f : 1.f;
    const float4* p = (const float4*)(flow + ((size_t)x * NXY + y) * 48);

    float4 fx4 = p[q];
    float4 fy4 = p[q + 6];
    float fxs[4] = {fx4.x, fx4.y, fx4.z, fx4.w};
    float fys[4] = {fy4.x, fy4.y, fy4.z, fy4.w};
    #pragma unroll
    for (int u = 0; u < 4; ++u) {
        int t = 4*q + u;
        float px = fminf(fmaxf((float)x + fxs[u], 0.f), 255.f);
        float py = fminf(fmaxf((float)y + fys[u], 0.f), 255.f);
        int x0 = (int)floorf(px); if (x0 > 254) x0 = 254;
        int y0 = (int)floorf(py); if (y0 > 254) y0 = 254;
        float wx = px - (float)x0, wy = py - (float)y0;
        int b = x0 * NXY + y0;
        float a0 = (1.f - wx) * (1.f - wy);
        float a1 = (1.f - wx) * wy;
        float a2 = wx * (1.f - wy);
        float a3 = wx * wy;
        float re = a0*ir[b] + a1*ir[b+1] + a2*ir[b+NXY] + a3*ir[b+NXY+1];
        float im = a0*ii[b] + a1*ii[b+1] + a2*ii[b+NXY] + a3*ii[b+NXY+1];
        g_warped[t][x][y] = make_float2(sgn * re, sgn * im);
    }
}

// ---------------- kernel 2: smaps -> [c][x][y] float2 --------------------------
__global__ void __launch_bounds__(256) smaps_kernel(const float* __restrict__ sr,
                                                    const float* __restrict__ si)
{
    const int x = blockIdx.x;
    const int y = threadIdx.x;
    const int h = blockIdx.y;                 // half: coils 8h..8h+7
    const float4* pr = (const float4*)(sr + ((size_t)x * NXY + y) * NC);
    const float4* pi = (const float4*)(si + ((size_t)x * NXY + y) * NC);
    float r[8], m[8];
    #pragma unroll
    for (int q = 0; q < 2; ++q) {
        float4 a = pr[2*h + q]; r[4*q]=a.x; r[4*q+1]=a.y; r[4*q+2]=a.z; r[4*q+3]=a.w;
        float4 b = pi[2*h + q]; m[4*q]=b.x; m[4*q+1]=b.y; m[4*q+2]=b.z; m[4*q+3]=b.w;
    }
    #pragma unroll
    for (int c = 0; c < 8; ++c)
        g_smapsT[8*h + c][x][y] = make_float2(r[c], m[c]);
}

// ---------------- kernel 3: row FFT along y, write transposed G ----------------
__global__ void __launch_bounds__(256) stage2_kernel(int c0)
{
    __shared__ float2 tile[256][8];           // [ky][swizzled xl]
    __shared__ float2 tw[256];
    const int tid = threadIdx.x;
    {
        float s, c;
        sincosf(-6.283185307179586f * (float)tid / 256.f, &s, &c);
        tw[tid] = make_float2(c, s);
    }
    __syncthreads();

    const int warpi = tid >> 5, L = tid & 31;
    const int xb = blockIdx.x, t = blockIdx.y, buf = blockIdx.z;
    const int c = c0 + buf;
    const int x = xb * 8 + warpi;

    const float2* wr = &g_warped[t][x][0];
    const float2* sm = &g_smapsT[c][x][0];
    float2 v[8];
    #pragma unroll
    for (int j = 0; j < 8; ++j) v[j] = cmul(wr[32*j + L], sm[32*j + L]);

    fft256(v, L, tw);

    const int R = __brev((unsigned)L) >> 27;
    const int RJ[8] = {0,4,2,6,1,5,3,7};
    #pragma unroll
    for (int j = 0; j < 8; ++j) {
        int pos = 8*R + RJ[j];
        tile[pos][(warpi + pos + (pos >> 3)) & 7] = v[j];
    }
    __syncthreads();

    float2* dst = &g_G[buf][t][0][xb * 8];
    #pragma unroll
    for (int i = 0; i < 8; ++i) {
        int idx = tid + i * 256;
        int ky = idx >> 3, xl = idx & 7;
        dst[(size_t)ky * NXY + xl] = tile[ky][(xl + ky + (ky >> 3)) & 7];
    }
}

// ---------------- kernel 4: column FFT along x + masked t-sum ------------------
__global__ void __launch_bounds__(256, 5) stage3_kernel(const float* __restrict__ mask,
                                                        int c0)
{
    __shared__ float2 K[8][256];              // 8 timepoints at a time
    __shared__ float2 tw[256];
    const int tid = threadIdx.x;
    {
        float s, c;
        sincosf(-6.283185307179586f * (float)tid / 256.f, &s, &c);
        tw[tid] = make_float2(c, s);
    }
    __syncthreads();

    const int ky = blockIdx.x, buf = blockIdx.y;
    const int c = c0 + buf;
    const int warpi = tid >> 5, L = tid & 31;
    const int RJ[8] = {0,4,2,6,1,5,3,7};
    const int kx = tid;
    const int sx = swz2(kx);
    const float4* m4 = (const float4*)(mask + ((((size_t)kx * NXY + ky) * NC + c) * NT));

    float ax = 0.f, ay = 0.f;
    #pragma unroll
    for (int q = 0; q < 3; ++q) {
        const int t = q * 8 + warpi;
        const float2* src = &g_G[buf][t][ky][0];
        float2 v[8];
        #pragma unroll
        for (int j = 0; j < 8; ++j) v[j] = src[32*j + L];
        fft256(v, L, tw);
        const int R = __brev((unsigned)L) >> 27;
        if (q) __syncthreads();               // protect K from overwrite
        #pragma unroll
        for (int j = 0; j < 8; ++j)
            K[warpi][swz2(8*R + RJ[j])] = v[j];
        __syncthreads();

        float4 f0 = __ldcs(m4 + 2*q);
        float4 f1 = __ldcs(m4 + 2*q + 1);
        float mm[8] = {f0.x, f0.y, f0.z, f0.w, f1.x, f1.y, f1.z, f1.w};
        #pragma unroll
        for (int tl = 0; tl < 8; ++tl) {
            float2 kv = K[tl][sx];
            ax = fmaf(kv.x, mm[tl], ax);
            ay = fmaf(kv.y, mm[tl], ay);
        }
    }
    const float s = ((kx + ky) & 1) ? -0.00390625f : 0.00390625f;   // (-1)^(kx+ky)/256
    g_outT[c][ky][kx] = make_float2(ax * s, ay * s);
}

// ---------------- kernel 5: repack to [2][Nx][Ny][Nc] --------------------------
__global__ void __launch_bounds__(256) final_kernel(float* __restrict__ out)
{
    const int x = blockIdx.x;
    const int y = threadIdx.x;
    const int h = blockIdx.y;                 // coils 8h..8h+7
    float re[8], im[8];
    #pragma unroll
    for (int c = 0; c < 8; ++c) {
        float2 v = g_outT[8*h + c][y][x];
        re[c] = v.x; im[c] = v.y;
    }
    float* pr = out + ((size_t)x * NXY + y) * NC + 8*h;
    float* pi = pr + (size_t)NXY * NXY * NC;
    #pragma unroll
    for (int q = 0; q < 2; ++q) {
        ((float4*)pr)[q] = make_float4(re[4*q], re[4*q+1], re[4*q+2], re[4*q+3]);
        ((float4*)pi)[q] = make_float4(im[4*q], im[4*q+1], im[4*q+2], im[4*q+3]);
    }
}

// ---------------- launch -------------------------------------------------------
extern "C" void kernel_launch(void* const* d_in, const int* in_sizes, int n_in,
                              void* d_out, int out_size)
{
    (void)in_sizes; (void)n_in; (void)out_size;
    const float* image_real = (const float*)d_in[0];
    const float* image_imag = (const float*)d_in[1];
    const float* mask       = (const float*)d_in[2];
    const float* smaps_real = (const float*)d_in[3];
    const float* smaps_imag = (const float*)d_in[4];
    const float* flow       = (const float*)d_in[5];

    warp_kernel <<<dim3(256, 6), 256>>>(image_real, image_imag, flow);
    smaps_kernel<<<dim3(256, 2), 256>>>(smaps_real, smaps_imag);
    for (int c0 = 0; c0 < NC; c0 += GRP) {
        stage2_kernel<<<dim3(32, NT, GRP), 256>>>(c0);
        stage3_kernel<<<dim3(256, GRP), 256>>>(mask, c0);
    }
    final_kernel<<<dim3(256, 2), 256>>>((float*)d_out);
}

// round 3
// speedup vs baseline: 1.5445x; 1.1674x over previous
#include <cuda_runtime.h>
#include <math.h>

#define NXY 256
#define NT  24
#define NC  16
#define GRP 4      // coils per group (G slice stays L2-resident)

// ---------------- scratch ------------------------------------------------------
__device__ float2 g_warped[NT][NXY][NXY];      // (-1)^(x+y) * warp_t(img)   12.6 MB
__device__ float2 g_smapsT[NC][NXY][NXY];      // smaps [c][x][y]             8.4 MB
__device__ float2 g_G[GRP][NT][NXY][NXY];      // row-FFT interm, reused     50.3 MB
__device__ float2 g_outT[NC][NXY][NXY];        // result [c][ky][kx]          8.4 MB

// ---------------- complex helpers ---------------------------------------------
__device__ __forceinline__ float2 cmul(float2 a, float2 b){
    return make_float2(fmaf(a.x, b.x, -a.y*b.y), fmaf(a.x, b.y, a.y*b.x));
}
__device__ __forceinline__ float2 cadd(float2 a, float2 b){ return make_float2(a.x+b.x, a.y+b.y); }
__device__ __forceinline__ float2 csub(float2 a, float2 b){ return make_float2(a.x-b.x, a.y-b.y); }

__device__ __forceinline__ int swz2(int k){ return (k & ~7) | ((k + (k >> 3) + (k >> 6)) & 7); }

// in-register radix-8 DIF butterfly; slot j ends up holding k1 = RJ[j]
// RJ = {0,4,2,6,1,5,3,7}
__device__ __forceinline__ void radix8(float2 v[8])
{
    const float S2 = 0.70710678118654752f;
    float2 s0=cadd(v[0],v[4]), d0=csub(v[0],v[4]);
    float2 s1=cadd(v[1],v[5]), d1=csub(v[1],v[5]);
    float2 s2=cadd(v[2],v[6]), d2=csub(v[2],v[6]);
    float2 s3=cadd(v[3],v[7]), d3=csub(v[3],v[7]);
    d1 = cmul(d1, make_float2( S2,-S2));
    d2 = make_float2(d2.y, -d2.x);
    d3 = cmul(d3, make_float2(-S2,-S2));
    float2 e0=cadd(s0,s2), f0=csub(s0,s2);
    float2 e1=cadd(s1,s3), f1=csub(s1,s3);
    f1 = make_float2(f1.y, -f1.x);
    float2 e2=cadd(d0,d2), f2=csub(d0,d2);
    float2 e3=cadd(d1,d3), f3=csub(d1,d3);
    f3 = make_float2(f3.y, -f3.x);
    v[0]=cadd(e0,e1); v[1]=csub(e0,e1);
    v[2]=cadd(f0,f1); v[3]=csub(f0,f1);
    v[4]=cadd(e2,e3); v[5]=csub(e2,e3);
    v[6]=cadd(f2,f3); v[7]=csub(f2,f3);
}

// multiply slot holding k=e by wbase^e, e=1..7 (slot with k=e is IDX[e])
__device__ __forceinline__ void twiddle_chain(float2 v[8], float2 wb)
{
    float2 w = wb;
    v[4] = cmul(v[4], w);
    w = cmul(w, wb); v[2] = cmul(v[2], w);
    w = cmul(w, wb); v[6] = cmul(v[6], w);
    w = cmul(w, wb); v[1] = cmul(v[1], w);
    w = cmul(w, wb); v[5] = cmul(v[5], w);
    w = cmul(w, wb); v[3] = cmul(v[3], w);
    w = cmul(w, wb); v[7] = cmul(v[7], w);
}

// ---------------- 256-pt FFT, one warp, 8 pts/thread, low-MIO version ----------
// Input : v[j] = x[32*j + L]
// Output: slot m of lane L holds X[RJ[L&7] + 8*RJ[m] + 64*rev2(L>>3)]
// scr: per-warp scratch, 32 rows x 10 float2 (stride 10 kills bank conflicts)
// wA = exp(-2pi i L/256),  wB = exp(-2pi i 8*(L>>3)/256)
__device__ __forceinline__ void fft256_v2(float2 v[8], int L,
                                          float2* __restrict__ scr,
                                          float2 wA, float2 wB)
{
    // phase A: radix-8 over register dim + twiddle w256^(L*k1)
    radix8(v);
    twiddle_chain(v, wA);

    // warp-private transpose: scr[n2=L][j] = v[j]
    __syncwarp();
    float4* row = (float4*)(scr + L * 10);
    row[0] = make_float4(v[0].x, v[0].y, v[1].x, v[1].y);
    row[1] = make_float4(v[2].x, v[2].y, v[3].x, v[3].y);
    row[2] = make_float4(v[4].x, v[4].y, v[5].x, v[5].y);
    row[3] = make_float4(v[6].x, v[6].y, v[7].x, v[7].y);
    __syncwarp();
    const int jj = L & 7, q = L >> 3;
    const float2* col = scr + (q * 10 + jj);
    #pragma unroll
    for (int m = 0; m < 8; ++m) v[m] = col[m * 40];   // scr[(4m+q)*10 + jj]

    // phase B: radix-8 over register dim + twiddle w32^(q*p1)
    radix8(v);
    twiddle_chain(v, wB);

    // FFT-4 across lane quarters (xor 16 then xor 8)
    const bool hi1 = (L & 16) != 0;
    #pragma unroll
    for (int m = 0; m < 8; ++m) {
        float ox = __shfl_xor_sync(0xffffffffu, v[m].x, 16);
        float oy = __shfl_xor_sync(0xffffffffu, v[m].y, 16);
        v[m] = hi1 ? make_float2(ox - v[m].x, oy - v[m].y)
                   : make_float2(v[m].x + ox, v[m].y + oy);
    }
    if (q == 3) {
        #pragma unroll
        for (int m = 0; m < 8; ++m) v[m] = make_float2(v[m].y, -v[m].x);  // * -i
    }
    const bool hi0 = (L & 8) != 0;
    #pragma unroll
    for (int m = 0; m < 8; ++m) {
        float ox = __shfl_xor_sync(0xffffffffu, v[m].x, 8);
        float oy = __shfl_xor_sync(0xffffffffu, v[m].y, 8);
        v[m] = hi0 ? make_float2(ox - v[m].x, oy - v[m].y)
                   : make_float2(v[m].x + ox, v[m].y + oy);
    }
}

__device__ __forceinline__ int rev2i(int q){ return ((q & 1) << 1) | (q >> 1); }

// ---------------- kernel 1: bilinear warp, fold (-1)^(x+y) ---------------------
__global__ void __launch_bounds__(256) warp_kernel(const float* __restrict__ ir,
                                                   const float* __restrict__ ii,
                                                   const float* __restrict__ flow)
{
    const int x = blockIdx.x;
    const int y = threadIdx.x;
    const int q = blockIdx.y;                 // t-quad
    const float sgn = ((x + y) & 1) ? -1.f : 1.f;
    const float4* p = (const float4*)(flow + ((size_t)x * NXY + y) * 48);

    float4 fx4 = p[q];
    float4 fy4 = p[q + 6];
    float fxs[4] = {fx4.x, fx4.y, fx4.z, fx4.w};
    float fys[4] = {fy4.x, fy4.y, fy4.z, fy4.w};
    #pragma unroll
    for (int u = 0; u < 4; ++u) {
        int t = 4*q + u;
        float px = fminf(fmaxf((float)x + fxs[u], 0.f), 255.f);
        float py = fminf(fmaxf((float)y + fys[u], 0.f), 255.f);
        int x0 = (int)floorf(px); if (x0 > 254) x0 = 254;
        int y0 = (int)floorf(py); if (y0 > 254) y0 = 254;
        float wx = px - (float)x0, wy = py - (float)y0;
        int b = x0 * NXY + y0;
        float a0 = (1.f - wx) * (1.f - wy);
        float a1 = (1.f - wx) * wy;
        float a2 = wx * (1.f - wy);
        float a3 = wx * wy;
        float re = a0*ir[b] + a1*ir[b+1] + a2*ir[b+NXY] + a3*ir[b+NXY+1];
        float im = a0*ii[b] + a1*ii[b+1] + a2*ii[b+NXY] + a3*ii[b+NXY+1];
        g_warped[t][x][y] = make_float2(sgn * re, sgn * im);
    }
}

// ---------------- kernel 2: smaps -> [c][x][y] float2 --------------------------
__global__ void __launch_bounds__(256) smaps_kernel(const float* __restrict__ sr,
                                                    const float* __restrict__ si)
{
    const int x = blockIdx.x;
    const int y = threadIdx.x;
    const int h = blockIdx.y;
    const float4* pr = (const float4*)(sr + ((size_t)x * NXY + y) * NC);
    const float4* pi = (const float4*)(si + ((size_t)x * NXY + y) * NC);
    float r[8], m[8];
    #pragma unroll
    for (int q = 0; q < 2; ++q) {
        float4 a = pr[2*h + q]; r[4*q]=a.x; r[4*q+1]=a.y; r[4*q+2]=a.z; r[4*q+3]=a.w;
        float4 b = pi[2*h + q]; m[4*q]=b.x; m[4*q+1]=b.y; m[4*q+2]=b.z; m[4*q+3]=b.w;
    }
    #pragma unroll
    for (int c = 0; c < 8; ++c)
        g_smapsT[8*h + c][x][y] = make_float2(r[c], m[c]);
}

// ---------------- kernel 3: row FFT along y, write transposed G ----------------
__global__ void __launch_bounds__(256) stage2_kernel(int c0)
{
    __shared__ float2 tile[256][8];           // [ky][swizzled xl]
    __shared__ float2 scr[8][320];            // per-warp FFT transpose scratch

    const int tid = threadIdx.x;
    const int warpi = tid >> 5, L = tid & 31;
    const int jj = L & 7, q = L >> 3;

    float2 wA, wB;
    {
        const float ang = -6.283185307179586f / 256.f;
        float s, c;
        sincosf(ang * (float)L, &s, &c);        wA = make_float2(c, s);
        sincosf(ang * (float)(8 * q), &s, &c);  wB = make_float2(c, s);
    }

    const int xb = blockIdx.x, t = blockIdx.y, buf = blockIdx.z;
    const int c = c0 + buf;
    const int x = xb * 8 + warpi;

    const float2* wr = &g_warped[t][x][0];
    const float2* sm = &g_smapsT[c][x][0];
    float2 v[8];
    #pragma unroll
    for (int j = 0; j < 8; ++j) v[j] = cmul(wr[32*j + L], sm[32*j + L]);

    fft256_v2(v, L, &scr[warpi][0], wA, wB);

    const int RJ[8] = {0,4,2,6,1,5,3,7};
    const int pbase = RJ[jj] + 64 * rev2i(q);
    #pragma unroll
    for (int m = 0; m < 8; ++m) {
        int pos = pbase + 8 * RJ[m];
        tile[pos][(warpi + pos + (pos >> 3)) & 7] = v[m];
    }
    __syncthreads();

    float2* dst = &g_G[buf][t][0][xb * 8];
    #pragma unroll
    for (int i = 0; i < 8; ++i) {
        int idx = tid + i * 256;
        int ky = idx >> 3, xl = idx & 7;
        dst[(size_t)ky * NXY + xl] = tile[ky][(xl + ky + (ky >> 3)) & 7];
    }
}

// ---------------- kernel 4: column FFT along x + masked t-sum ------------------
__global__ void __launch_bounds__(256) stage3_kernel(const float* __restrict__ mask,
                                                     int c0)
{
    __shared__ float2 K[8][256];
    __shared__ float2 scr[8][320];

    const int tid = threadIdx.x;
    const int warpi = tid >> 5, L = tid & 31;
    const int jj = L & 7, q = L >> 3;

    float2 wA, wB;
    {
        const float ang = -6.283185307179586f / 256.f;
        float s, c;
        sincosf(ang * (float)L, &s, &c);        wA = make_float2(c, s);
        sincosf(ang * (float)(8 * q), &s, &c);  wB = make_float2(c, s);
    }

    const int ky = blockIdx.x, buf = blockIdx.y;
    const int c = c0 + buf;
    const int RJ[8] = {0,4,2,6,1,5,3,7};
    const int pbase = RJ[jj] + 64 * rev2i(q);
    const int kx = tid;
    const int sx = swz2(kx);
    const float4* m4 = (const float4*)(mask + ((((size_t)kx * NXY + ky) * NC + c) * NT));

    float ax = 0.f, ay = 0.f;
    #pragma unroll
    for (int qq = 0; qq < 3; ++qq) {
        const int t = qq * 8 + warpi;
        const float2* src = &g_G[buf][t][ky][0];
        float2 v[8];
        #pragma unroll
        for (int j = 0; j < 8; ++j) v[j] = src[32*j + L];
        fft256_v2(v, L, &scr[warpi][0], wA, wB);
        if (qq) __syncthreads();
        #pragma unroll
        for (int m = 0; m < 8; ++m)
            K[warpi][swz2(pbase + 8 * RJ[m])] = v[m];
        __syncthreads();

        float4 f0 = __ldcs(m4 + 2*qq);
        float4 f1 = __ldcs(m4 + 2*qq + 1);
        float mm[8] = {f0.x, f0.y, f0.z, f0.w, f1.x, f1.y, f1.z, f1.w};
        #pragma unroll
        for (int tl = 0; tl < 8; ++tl) {
            float2 kv = K[tl][sx];
            ax = fmaf(kv.x, mm[tl], ax);
            ay = fmaf(kv.y, mm[tl], ay);
        }
    }
    const float s = ((kx + ky) & 1) ? -0.00390625f : 0.00390625f;   // (-1)^(kx+ky)/256
    g_outT[c][ky][kx] = make_float2(ax * s, ay * s);
}

// ---------------- kernel 5: repack to [2][Nx][Ny][Nc] --------------------------
__global__ void __launch_bounds__(256) final_kernel(float* __restrict__ out)
{
    const int x = blockIdx.x;
    const int y = threadIdx.x;
    const int h = blockIdx.y;
    float re[8], im[8];
    #pragma unroll
    for (int c = 0; c < 8; ++c) {
        float2 v = g_outT[8*h + c][y][x];
        re[c] = v.x; im[c] = v.y;
    }
    float* pr = out + ((size_t)x * NXY + y) * NC + 8*h;
    float* pi = pr + (size_t)NXY * NXY * NC;
    #pragma unroll
    for (int q = 0; q < 2; ++q) {
        ((float4*)pr)[q] = make_float4(re[4*q], re[4*q+1], re[4*q+2], re[4*q+3]);
        ((float4*)pi)[q] = make_float4(im[4*q], im[4*q+1], im[4*q+2], im[4*q+3]);
    }
}

// ---------------- launch -------------------------------------------------------
extern "C" void kernel_launch(void* const* d_in, const int* in_sizes, int n_in,
                              void* d_out, int out_size)
{
    (void)in_sizes; (void)n_in; (void)out_size;
    const float* image_real = (const float*)d_in[0];
    const float* image_imag = (const float*)d_in[1];
    const float* mask       = (const float*)d_in[2];
    const float* smaps_real = (const float*)d_in[3];
    const float* smaps_imag = (const float*)d_in[4];
    const float* flow       = (const float*)d_in[5];

    warp_kernel <<<dim3(256, 6), 256>>>(image_real, image_imag, flow);
    smaps_kernel<<<dim3(256, 2), 256>>>(smaps_real, smaps_imag);
    for (int c0 = 0; c0 < NC; c0 += GRP) {
        stage2_kernel<<<dim3(32, NT, GRP), 256>>>(c0);
        stage3_kernel<<<dim3(256, GRP), 256>>>(mask, c0);
    }
    final_kernel<<<dim3(256, 2), 256>>>((float*)d_out);
}

// round 4
// speedup vs baseline: 1.6495x; 1.0680x over previous
#include <cuda_runtime.h>
#include <math.h>

#define NXY 256
#define NT  24
#define NC  16
#define GRP 4      // coils per group (G slice stays L2-resident)

// ---------------- scratch ------------------------------------------------------
__device__ float2 g_warped[NT][NXY][NXY];      // (-1)^(x+y) * warp_t(img)   12.6 MB
__device__ float2 g_smapsT[NC][NXY][NXY];      // smaps [c][x][y]             8.4 MB
__device__ float2 g_G[GRP][NT][NXY][NXY];      // row-FFT interm, reused     50.3 MB
__device__ float2 g_outT[NC][NXY][NXY];        // result [c][ky][kx]          8.4 MB

// ---------------- complex helpers ---------------------------------------------
__device__ __forceinline__ float2 cmul(float2 a, float2 b){
    return make_float2(fmaf(a.x, b.x, -a.y*b.y), fmaf(a.x, b.y, a.y*b.x));
}
__device__ __forceinline__ float2 cadd(float2 a, float2 b){ return make_float2(a.x+b.x, a.y+b.y); }
__device__ __forceinline__ float2 csub(float2 a, float2 b){ return make_float2(a.x-b.x, a.y-b.y); }

__device__ __forceinline__ int swz2(int k){ return (k & ~7) | ((k + (k >> 3) + (k >> 6)) & 7); }

// in-register radix-8 DIF butterfly; slot j ends up holding k1 = RJ[j]
// RJ = {0,4,2,6,1,5,3,7}
__device__ __forceinline__ void radix8(float2 v[8])
{
    const float S2 = 0.70710678118654752f;
    float2 s0=cadd(v[0],v[4]), d0=csub(v[0],v[4]);
    float2 s1=cadd(v[1],v[5]), d1=csub(v[1],v[5]);
    float2 s2=cadd(v[2],v[6]), d2=csub(v[2],v[6]);
    float2 s3=cadd(v[3],v[7]), d3=csub(v[3],v[7]);
    d1 = cmul(d1, make_float2( S2,-S2));
    d2 = make_float2(d2.y, -d2.x);
    d3 = cmul(d3, make_float2(-S2,-S2));
    float2 e0=cadd(s0,s2), f0=csub(s0,s2);
    float2 e1=cadd(s1,s3), f1=csub(s1,s3);
    f1 = make_float2(f1.y, -f1.x);
    float2 e2=cadd(d0,d2), f2=csub(d0,d2);
    float2 e3=cadd(d1,d3), f3=csub(d1,d3);
    f3 = make_float2(f3.y, -f3.x);
    v[0]=cadd(e0,e1); v[1]=csub(e0,e1);
    v[2]=cadd(f0,f1); v[3]=csub(f0,f1);
    v[4]=cadd(e2,e3); v[5]=csub(e2,e3);
    v[6]=cadd(f2,f3); v[7]=csub(f2,f3);
}

// multiply slot holding k=e by wbase^e, e=1..7
__device__ __forceinline__ void twiddle_chain(float2 v[8], float2 wb)
{
    float2 w = wb;
    v[4] = cmul(v[4], w);
    w = cmul(w, wb); v[2] = cmul(v[2], w);
    w = cmul(w, wb); v[6] = cmul(v[6], w);
    w = cmul(w, wb); v[1] = cmul(v[1], w);
    w = cmul(w, wb); v[5] = cmul(v[5], w);
    w = cmul(w, wb); v[3] = cmul(v[3], w);
    w = cmul(w, wb); v[7] = cmul(v[7], w);
}

// ---------------- 256-pt FFT, one warp, 8 pts/thread ---------------------------
// Input : v[j] = x[32*j + L]
// Output: slot m of lane L holds X[RJ[L&7] + 8*RJ[m] + 64*rev2(L>>3)]
// scr: per-warp scratch, 32 rows x 10 float2
// NOTE: scratch use ends before return, but callers must __syncthreads() before
// writing anything that aliases another warp's scr region.
__device__ __forceinline__ void fft256_v2(float2 v[8], int L,
                                          float2* __restrict__ scr,
                                          float2 wA, float2 wB)
{
    radix8(v);
    twiddle_chain(v, wA);

    __syncwarp();
    float4* row = (float4*)(scr + L * 10);
    row[0] = make_float4(v[0].x, v[0].y, v[1].x, v[1].y);
    row[1] = make_float4(v[2].x, v[2].y, v[3].x, v[3].y);
    row[2] = make_float4(v[4].x, v[4].y, v[5].x, v[5].y);
    row[3] = make_float4(v[6].x, v[6].y, v[7].x, v[7].y);
    __syncwarp();
    const int jj = L & 7, q = L >> 3;
    const float2* col = scr + (q * 10 + jj);
    #pragma unroll
    for (int m = 0; m < 8; ++m) v[m] = col[m * 40];

    radix8(v);
    twiddle_chain(v, wB);

    const bool hi1 = (L & 16) != 0;
    #pragma unroll
    for (int m = 0; m < 8; ++m) {
        float ox = __shfl_xor_sync(0xffffffffu, v[m].x, 16);
        float oy = __shfl_xor_sync(0xffffffffu, v[m].y, 16);
        v[m] = hi1 ? make_float2(ox - v[m].x, oy - v[m].y)
                   : make_float2(v[m].x + ox, v[m].y + oy);
    }
    if (q == 3) {
        #pragma unroll
        for (int m = 0; m < 8; ++m) v[m] = make_float2(v[m].y, -v[m].x);
    }
    const bool hi0 = (L & 8) != 0;
    #pragma unroll
    for (int m = 0; m < 8; ++m) {
        float ox = __shfl_xor_sync(0xffffffffu, v[m].x, 8);
        float oy = __shfl_xor_sync(0xffffffffu, v[m].y, 8);
        v[m] = hi0 ? make_float2(ox - v[m].x, oy - v[m].y)
                   : make_float2(v[m].x + ox, v[m].y + oy);
    }
}

__device__ __forceinline__ int rev2i(int q){ return ((q & 1) << 1) | (q >> 1); }

// ---------------- kernel 1: bilinear warp, fold (-1)^(x+y) ---------------------
__global__ void __launch_bounds__(256) warp_kernel(const float* __restrict__ ir,
                                                   const float* __restrict__ ii,
                                                   const float* __restrict__ flow)
{
    const int x = blockIdx.x;
    const int y = threadIdx.x;
    const int q = blockIdx.y;
    const float sgn = ((x + y) & 1) ? -1.f : 1.f;
    const float4* p = (const float4*)(flow + ((size_t)x * NXY + y) * 48);

    float4 fx4 = p[q];
    float4 fy4 = p[q + 6];
    float fxs[4] = {fx4.x, fx4.y, fx4.z, fx4.w};
    float fys[4] = {fy4.x, fy4.y, fy4.z, fy4.w};
    #pragma unroll
    for (int u = 0; u < 4; ++u) {
        int t = 4*q + u;
        float px = fminf(fmaxf((float)x + fxs[u], 0.f), 255.f);
        float py = fminf(fmaxf((float)y + fys[u], 0.f), 255.f);
        int x0 = (int)floorf(px); if (x0 > 254) x0 = 254;
        int y0 = (int)floorf(py); if (y0 > 254) y0 = 254;
        float wx = px - (float)x0, wy = py - (float)y0;
        int b = x0 * NXY + y0;
        float a0 = (1.f - wx) * (1.f - wy);
        float a1 = (1.f - wx) * wy;
        float a2 = wx * (1.f - wy);
        float a3 = wx * wy;
        float re = a0*ir[b] + a1*ir[b+1] + a2*ir[b+NXY] + a3*ir[b+NXY+1];
        float im = a0*ii[b] + a1*ii[b+1] + a2*ii[b+NXY] + a3*ii[b+NXY+1];
        g_warped[t][x][y] = make_float2(sgn * re, sgn * im);
    }
}

// ---------------- kernel 2: smaps -> [c][x][y] float2 --------------------------
__global__ void __launch_bounds__(256) smaps_kernel(const float* __restrict__ sr,
                                                    const float* __restrict__ si)
{
    const int x = blockIdx.x;
    const int y = threadIdx.x;
    const int h = blockIdx.y;
    const float4* pr = (const float4*)(sr + ((size_t)x * NXY + y) * NC);
    const float4* pi = (const float4*)(si + ((size_t)x * NXY + y) * NC);
    float r[8], m[8];
    #pragma unroll
    for (int q = 0; q < 2; ++q) {
        float4 a = pr[2*h + q]; r[4*q]=a.x; r[4*q+1]=a.y; r[4*q+2]=a.z; r[4*q+3]=a.w;
        float4 b = pi[2*h + q]; m[4*q]=b.x; m[4*q+1]=b.y; m[4*q+2]=b.z; m[4*q+3]=b.w;
    }
    #pragma unroll
    for (int c = 0; c < 8; ++c)
        g_smapsT[8*h + c][x][y] = make_float2(r[c], m[c]);
}

// ---------------- kernel 3: row FFT along y, write transposed G ----------------
// smem union: scr (8 warps x 320 f2 = 20 KB) aliases tile (256x8 f2 = 16 KB);
// temporally separated by __syncthreads().
__global__ void __launch_bounds__(256, 4) stage2_kernel(int c0)
{
    __shared__ float2 B[8 * 320];             // 20 KB union buffer
    const int tid = threadIdx.x;
    const int warpi = tid >> 5, L = tid & 31;
    const int jj = L & 7, q = L >> 3;

    float2 wA, wB;
    {
        const float ang = -6.283185307179586f / 256.f;
        float s, c;
        __sincosf(ang * (float)L, &s, &c);        wA = make_float2(c, s);
        __sincosf(ang * (float)(8 * q), &s, &c);  wB = make_float2(c, s);
    }

    const int xb = blockIdx.x, t = blockIdx.y, buf = blockIdx.z;
    const int c = c0 + buf;
    const int x = xb * 8 + warpi;

    const float2* wr = &g_warped[t][x][0];
    const float2* sm = &g_smapsT[c][x][0];
    float2 v[8];
    #pragma unroll
    for (int j = 0; j < 8; ++j) v[j] = cmul(wr[32*j + L], sm[32*j + L]);

    fft256_v2(v, L, B + warpi * 320, wA, wB);

    __syncthreads();                           // scr phase done (all warps)

    const int RJ[8] = {0,4,2,6,1,5,3,7};
    const int pbase = RJ[jj] + 64 * rev2i(q);
    #pragma unroll
    for (int m = 0; m < 8; ++m) {
        int pos = pbase + 8 * RJ[m];
        B[pos * 8 + ((warpi + pos + (pos >> 3)) & 7)] = v[m];   // tile[pos][swz]
    }
    __syncthreads();

    float2* dst = &g_G[buf][t][0][xb * 8];
    #pragma unroll
    for (int i = 0; i < 8; ++i) {
        int idx = tid + i * 256;
        int ky = idx >> 3, xl = idx & 7;
        dst[(size_t)ky * NXY + xl] = B[ky * 8 + ((xl + ky + (ky >> 3)) & 7)];
    }
}

// ---------------- kernel 4: column FFT along x + masked t-sum ------------------
// smem union: scr (20 KB) aliases K (8x256 f2 = 16 KB); separated by syncs.
__global__ void __launch_bounds__(256, 4) stage3_kernel(const float* __restrict__ mask,
                                                        int c0)
{
    __shared__ float2 B[8 * 320];             // 20 KB union buffer

    const int tid = threadIdx.x;
    const int warpi = tid >> 5, L = tid & 31;
    const int jj = L & 7, q = L >> 3;

    float2 wA, wB;
    {
        const float ang = -6.283185307179586f / 256.f;
        float s, c;
        __sincosf(ang * (float)L, &s, &c);        wA = make_float2(c, s);
        __sincosf(ang * (float)(8 * q), &s, &c);  wB = make_float2(c, s);
    }

    const int ky = blockIdx.x, buf = blockIdx.y;
    const int c = c0 + buf;
    const int RJ[8] = {0,4,2,6,1,5,3,7};
    const int pbase = RJ[jj] + 64 * rev2i(q);
    const int kx = tid;
    const int sx = swz2(kx);
    const float4* m4 = (const float4*)(mask + ((((size_t)kx * NXY + ky) * NC + c) * NT));

    float ax = 0.f, ay = 0.f;
    #pragma unroll
    for (int qq = 0; qq < 3; ++qq) {
        if (qq) __syncthreads();               // prior K reads done before scr reuse
        const int t = qq * 8 + warpi;
        const float2* src = &g_G[buf][t][ky][0];
        float2 v[8];
        #pragma unroll
        for (int j = 0; j < 8; ++j) v[j] = src[32*j + L];
        fft256_v2(v, L, B + warpi * 320, wA, wB);
        __syncthreads();                       // scr phase done before K writes
        #pragma unroll
        for (int m = 0; m < 8; ++m)
            B[warpi * 256 + swz2(pbase + 8 * RJ[m])] = v[m];   // K[warpi][swz]
        __syncthreads();

        float4 f0 = __ldcs(m4 + 2*qq);
        float4 f1 = __ldcs(m4 + 2*qq + 1);
        float mm[8] = {f0.x, f0.y, f0.z, f0.w, f1.x, f1.y, f1.z, f1.w};
        #pragma unroll
        for (int tl = 0; tl < 8; ++tl) {
            float2 kv = B[tl * 256 + sx];
            ax = fmaf(kv.x, mm[tl], ax);
            ay = fmaf(kv.y, mm[tl], ay);
        }
    }
    const float s = ((kx + ky) & 1) ? -0.00390625f : 0.00390625f;   // (-1)^(kx+ky)/256
    g_outT[c][ky][kx] = make_float2(ax * s, ay * s);
}

// ---------------- kernel 5: repack to [2][Nx][Ny][Nc] --------------------------
__global__ void __launch_bounds__(256) final_kernel(float* __restrict__ out)
{
    const int x = blockIdx.x;
    const int y = threadIdx.x;
    const int h = blockIdx.y;
    float re[8], im[8];
    #pragma unroll
    for (int c = 0; c < 8; ++c) {
        float2 v = g_outT[8*h + c][y][x];
        re[c] = v.x; im[c] = v.y;
    }
    float* pr = out + ((size_t)x * NXY + y) * NC + 8*h;
    float* pi = pr + (size_t)NXY * NXY * NC;
    #pragma unroll
    for (int q = 0; q < 2; ++q) {
        ((float4*)pr)[q] = make_float4(re[4*q], re[4*q+1], re[4*q+2], re[4*q+3]);
        ((float4*)pi)[q] = make_float4(im[4*q], im[4*q+1], im[4*q+2], im[4*q+3]);
    }
}

// ---------------- launch -------------------------------------------------------
extern "C" void kernel_launch(void* const* d_in, const int* in_sizes, int n_in,
                              void* d_out, int out_size)
{
    (void)in_sizes; (void)n_in; (void)out_size;
    const float* image_real = (const float*)d_in[0];
    const float* image_imag = (const float*)d_in[1];
    const float* mask       = (const float*)d_in[2];
    const float* smaps_real = (const float*)d_in[3];
    const float* smaps_imag = (const float*)d_in[4];
    const float* flow       = (const float*)d_in[5];

    warp_kernel <<<dim3(256, 6), 256>>>(image_real, image_imag, flow);
    smaps_kernel<<<dim3(256, 2), 256>>>(smaps_real, smaps_imag);
    for (int c0 = 0; c0 < NC; c0 += GRP) {
        stage2_kernel<<<dim3(32, NT, GRP), 256>>>(c0);
        stage3_kernel<<<dim3(256, GRP), 256>>>(mask, c0);
    }
    final_kernel<<<dim3(256, 2), 256>>>((float*)d_out);
}